// round 6
// baseline (speedup 1.0000x reference)
#include <cuda_runtime.h>
#include <cuda_bf16.h>
#include <stdint.h>
#include <math.h>

// Problem constants (CrossAttention_7756710936941)
#define B_BATCH 2
#define LQ      2048
#define LK      2048
#define DIM     1024
#define DCTX    768
#define NH      16
#define HD      64
#define MROWS   (B_BATCH * LQ)

// q pre-scale: 1/sqrt(64) * log2(e)  (softmax done in base-2)
#define QSC 0.18033688011112042f

// Scratch (allocation-free: device globals)
__device__ float g_q[(size_t)MROWS * DIM];
__device__ float g_k[(size_t)MROWS * DIM];
__device__ float g_v[(size_t)MROWS * DIM];
__device__ float g_att[(size_t)MROWS * DIM];

// ---------------------------------------------------------------------------
// helpers
// ---------------------------------------------------------------------------
__device__ __forceinline__ uint32_t f2tf(float x) {
    uint32_t u;
    asm("cvt.rna.tf32.f32 %0, %1;" : "=r"(u) : "f"(x));
    return u;
}
__device__ __forceinline__ float f2tf_f(float x) { return __uint_as_float(f2tf(x)); }
__device__ __forceinline__ float ex2f(float x) {
    float y;
    asm("ex2.approx.f32 %0, %1;" : "=f"(y) : "f"(x));
    return y;
}

__device__ __forceinline__ void mma_tf32(float c[4],
    uint32_t a0, uint32_t a1, uint32_t a2, uint32_t a3, uint32_t b0, uint32_t b1)
{
    asm volatile(
        "mma.sync.aligned.m16n8k8.row.col.f32.tf32.tf32.f32 "
        "{%0,%1,%2,%3},{%4,%5,%6,%7},{%8,%9},{%0,%1,%2,%3};"
        : "+f"(c[0]), "+f"(c[1]), "+f"(c[2]), "+f"(c[3])
        : "r"(a0), "r"(a1), "r"(a2), "r"(a3), "r"(b0), "r"(b1));
}

__device__ __forceinline__ void mma_bf16(float c[4],
    uint32_t a0, uint32_t a1, uint32_t a2, uint32_t a3, uint32_t b0, uint32_t b1)
{
    asm volatile(
        "mma.sync.aligned.m16n8k16.row.col.f32.bf16.bf16.f32 "
        "{%0,%1,%2,%3},{%4,%5,%6,%7},{%8,%9},{%0,%1,%2,%3};"
        : "+f"(c[0]), "+f"(c[1]), "+f"(c[2]), "+f"(c[3])
        : "r"(a0), "r"(a1), "r"(a2), "r"(a3), "r"(b0), "r"(b1));
}

__device__ __forceinline__ uint32_t pack_bf16_hi(float x0, float x1, float& r0, float& r1) {
    __nv_bfloat162 h = __floats2bfloat162_rn(x0, x1);  // x0 -> low half (even k)
    r0 = x0 - __bfloat162float(h.x);
    r1 = x1 - __bfloat162float(h.y);
    uint32_t u; *(__nv_bfloat162*)&u = h; return u;
}
__device__ __forceinline__ uint32_t pack_bf16(float x0, float x1) {
    __nv_bfloat162 h = __floats2bfloat162_rn(x0, x1);
    uint32_t u; *(__nv_bfloat162*)&u = h; return u;
}

// ---------------------------------------------------------------------------
// bf16 3-term GEMM with bias: C = A @ Bw + bias   (~fp32 accuracy)
// 128x128 block, BK=16, 8 warps (4m x 2n), warp tile 32x64.
// rmode: 0 = plain f32 store; 1 = tf32-round; 2 = tf32-round(QSC*v)
// perm : 1 = permute output cols within 8-groups (c -> 2*(c&3)+(c>>2)),
//        enabling LDS.64 tf32 fragment loads in the attention kernel.
// ---------------------------------------------------------------------------
#define GKW 12

__global__ __launch_bounds__(256, 2) void gemm_bf16_3x(
    const float* __restrict__ A, const float* __restrict__ Bw,
    const float* __restrict__ bias, float* __restrict__ C,
    int M, int N, int K, int rmode, int perm)
{
    __shared__ uint32_t Ah[128 * GKW], Al[128 * GKW];
    __shared__ uint32_t Bh[128 * GKW], Bl[128 * GKW];

    const int t    = threadIdx.x;
    const int lane = t & 31;
    const int w    = t >> 5;
    const int g    = lane >> 2, tg = lane & 3;
    const int wm   = w >> 1,    wn = w & 1;
    const int m0   = blockIdx.y * 128, n0 = blockIdx.x * 128;

    float c[2][8][4];
#pragma unroll
    for (int i = 0; i < 2; i++)
#pragma unroll
        for (int j = 0; j < 8; j++)
#pragma unroll
            for (int e = 0; e < 4; e++) c[i][j][e] = 0.0f;

    const int ar  = t >> 1;          // A row 0..127
    const int akh = (t & 1) * 8;     // A k offset (8 floats)
    const int bn  = t & 127;         // B n col 0..127
    const int bkh = (t >> 7) * 8;    // B k offset (8 floats)
    const int sB  = ((bn >> 3) ^ (bn >> 4)) & 1;

    float apf[8], bpf[8];
    {
        float4 v0 = *(const float4*)(A + (size_t)(m0 + ar) * K + akh);
        float4 v1 = *(const float4*)(A + (size_t)(m0 + ar) * K + akh + 4);
        apf[0]=v0.x; apf[1]=v0.y; apf[2]=v0.z; apf[3]=v0.w;
        apf[4]=v1.x; apf[5]=v1.y; apf[6]=v1.z; apf[7]=v1.w;
#pragma unroll
        for (int j = 0; j < 8; j++)
            bpf[j] = Bw[(size_t)(bkh + j) * N + n0 + bn];
    }

    for (int k0 = 0; k0 < K; k0 += 16) {
        __syncthreads();
        {   // A: pack hi/lo, store [m][kword]
            uint32_t hw[4], lw[4];
#pragma unroll
            for (int p = 0; p < 4; p++) {
                float r0, r1;
                hw[p] = pack_bf16_hi(apf[2*p], apf[2*p+1], r0, r1);
                lw[p] = pack_bf16(r0, r1);
            }
            *(uint4*)&Ah[ar * GKW + (t & 1) * 4] = make_uint4(hw[0], hw[1], hw[2], hw[3]);
            *(uint4*)&Al[ar * GKW + (t & 1) * 4] = make_uint4(lw[0], lw[1], lw[2], lw[3]);
        }
        {   // B: pack hi/lo, store transposed [n][kword] with group swizzle
            uint32_t hw[4], lw[4];
#pragma unroll
            for (int p = 0; p < 4; p++) {
                float r0, r1;
                hw[p] = pack_bf16_hi(bpf[2*p], bpf[2*p+1], r0, r1);
                lw[p] = pack_bf16(r0, r1);
            }
            const int grp = ((t >> 7) ^ sB) * 4;
            *(uint4*)&Bh[bn * GKW + grp] = make_uint4(hw[0], hw[1], hw[2], hw[3]);
            *(uint4*)&Bl[bn * GKW + grp] = make_uint4(lw[0], lw[1], lw[2], lw[3]);
        }
        __syncthreads();

        if (k0 + 16 < K) {
            float4 v0 = *(const float4*)(A + (size_t)(m0 + ar) * K + k0 + 16 + akh);
            float4 v1 = *(const float4*)(A + (size_t)(m0 + ar) * K + k0 + 16 + akh + 4);
            apf[0]=v0.x; apf[1]=v0.y; apf[2]=v0.z; apf[3]=v0.w;
            apf[4]=v1.x; apf[5]=v1.y; apf[6]=v1.z; apf[7]=v1.w;
#pragma unroll
            for (int j = 0; j < 8; j++)
                bpf[j] = Bw[(size_t)(k0 + 16 + bkh + j) * N + n0 + bn];
        }

        uint32_t ah[2][4], al[2][4];
#pragma unroll
        for (int mt = 0; mt < 2; mt++) {
            const int rA = wm * 32 + mt * 16;
            ah[mt][0] = Ah[(rA + g) * GKW + tg];
            ah[mt][1] = Ah[(rA + g + 8) * GKW + tg];
            ah[mt][2] = Ah[(rA + g) * GKW + tg + 4];
            ah[mt][3] = Ah[(rA + g + 8) * GKW + tg + 4];
            al[mt][0] = Al[(rA + g) * GKW + tg];
            al[mt][1] = Al[(rA + g + 8) * GKW + tg];
            al[mt][2] = Al[(rA + g) * GKW + tg + 4];
            al[mt][3] = Al[(rA + g + 8) * GKW + tg + 4];
        }
#pragma unroll
        for (int nt = 0; nt < 8; nt++) {
            const int nB = wn * 64 + nt * 8 + g;
            const int s  = (nt & 1) ^ ((nt >> 1) & 1);
            uint32_t bh0 = Bh[nB * GKW + s * 4 + tg];
            uint32_t bh1 = Bh[nB * GKW + (1 - s) * 4 + tg];
            uint32_t bl0 = Bl[nB * GKW + s * 4 + tg];
            uint32_t bl1 = Bl[nB * GKW + (1 - s) * 4 + tg];
#pragma unroll
            for (int mt = 0; mt < 2; mt++) {
                mma_bf16(c[mt][nt], ah[mt][0], ah[mt][1], ah[mt][2], ah[mt][3], bh0, bh1);
                mma_bf16(c[mt][nt], ah[mt][0], ah[mt][1], ah[mt][2], ah[mt][3], bl0, bl1);
                mma_bf16(c[mt][nt], al[mt][0], al[mt][1], al[mt][2], al[mt][3], bh0, bh1);
            }
        }
    }

    // epilogue: bias + optional rounding + optional column-pair permutation
#pragma unroll
    for (int mt = 0; mt < 2; mt++) {
        const int r = m0 + wm * 32 + mt * 16 + g;
#pragma unroll
        for (int nt = 0; nt < 8; nt++) {
            const int grpb = n0 + wn * 64 + nt * 8;
            const int c0 = 2 * tg, c1 = 2 * tg + 1;   // logical cols in group
            float v0 = c[mt][nt][0] + bias[grpb + c0];
            float v1 = c[mt][nt][1] + bias[grpb + c1];
            float v2 = c[mt][nt][2] + bias[grpb + c0];
            float v3 = c[mt][nt][3] + bias[grpb + c1];
            if (rmode == 1) {
                v0 = f2tf_f(v0); v1 = f2tf_f(v1); v2 = f2tf_f(v2); v3 = f2tf_f(v3);
            } else if (rmode == 2) {
                v0 = f2tf_f(v0 * QSC); v1 = f2tf_f(v1 * QSC);
                v2 = f2tf_f(v2 * QSC); v3 = f2tf_f(v3 * QSC);
            }
            if (perm) {
                const int p0 = (c0 & 3) * 2 + (c0 >> 2);
                const int p1 = (c1 & 3) * 2 + (c1 >> 2);
                C[(size_t)r * N + grpb + p0]       = v0;
                C[(size_t)r * N + grpb + p1]       = v1;
                C[(size_t)(r + 8) * N + grpb + p0] = v2;
                C[(size_t)(r + 8) * N + grpb + p1] = v3;
            } else {
                *(float2*)(C + (size_t)r * N + grpb + c0)       = make_float2(v0, v1);
                *(float2*)(C + (size_t)(r + 8) * N + grpb + c0) = make_float2(v2, v3);
            }
        }
    }
}

// ---------------------------------------------------------------------------
// Flash cross-attention, tf32 mma.sync, cp.async double-buffered K/V.
// Inputs pre-rounded to tf32 by the GEMM epilogues; q pre-scaled (base-2
// softmax); q/k column-pair-permuted so tf32 fragments load as LDS.64.
// CTA = (b,h,128 q rows), 8 warps x 16 rows, Bc=64.
// ---------------------------------------------------------------------------
#define KSTR 68
#define VSTR 72
#define SM_Q  (128 * KSTR)
#define SM_K  (64 * KSTR)
#define SM_V  (64 * VSTR)
#define ATTN_SMEM_FLOATS (SM_Q + 2 * SM_K + 2 * SM_V)

__device__ __forceinline__ void cp_async16(uint32_t dst, const void* src) {
    asm volatile("cp.async.cg.shared.global [%0], [%1], 16;" :: "r"(dst), "l"(src));
}

__global__ __launch_bounds__(256, 2) void attn_mma4(
    const float* __restrict__ gq, const float* __restrict__ gk,
    const float* __restrict__ gv, float* __restrict__ gatt)
{
    extern __shared__ float sm[];
    float* Qs = sm;
    float* Kd = Qs + SM_Q;
    float* Vd = Kd + 2 * SM_K;
    const uint32_t smb   = (uint32_t)__cvta_generic_to_shared(sm);
    const uint32_t kdstB = smb + SM_Q * 4;
    const uint32_t vdstB = smb + (SM_Q + 2 * SM_K) * 4;

    const int t    = threadIdx.x;
    const int lane = t & 31;
    const int w    = t >> 5;
    const int g    = lane >> 2, tg = lane & 3;
    const int m0   = w * 16;
    const int bh   = blockIdx.x;
    const int b    = bh >> 4, h = bh & 15;
    const int qt   = blockIdx.y;

    const float* qb  = gq + ((size_t)b * LQ + qt * 128) * DIM + h * HD;
    const float* kbp = gk + (size_t)b * LK * DIM + h * HD;
    const float* vbp = gv + (size_t)b * LK * DIM + h * HD;

    // Q tile: verbatim copy (already scaled+rounded+permuted)
#pragma unroll
    for (int j = 0; j < 8; j++) {
        int it = t + 256 * j;
        int r = it >> 4, d = (it & 15) * 4;
        *(float4*)&Qs[r * KSTR + d] = *(const float4*)(qb + (size_t)r * DIM + d);
    }

    {   // prologue: async-load tile 0 into buf 0
#pragma unroll
        for (int j = 0; j < 4; j++) {
            int it = t + 256 * j;
            int r = it >> 4, c4 = (it & 15) * 4;
            cp_async16(kdstB + (uint32_t)(r * KSTR + c4) * 4, kbp + (size_t)r * DIM + c4);
            cp_async16(vdstB + (uint32_t)(r * VSTR + c4) * 4, vbp + (size_t)r * DIM + c4);
        }
        asm volatile("cp.async.commit_group;" ::: "memory");
    }

    float oacc[8][4];
#pragma unroll
    for (int dt = 0; dt < 8; dt++)
#pragma unroll
        for (int e = 0; e < 4; e++) oacc[dt][e] = 0.0f;
    float mrow0 = -1e30f, mrow1 = -1e30f, lrow0 = 0.0f, lrow1 = 0.0f;

    for (int kt = 0; kt < LK / 64; kt++) {
        asm volatile("cp.async.wait_group 0;" ::: "memory");
        __syncthreads();

        if (kt + 1 < LK / 64) {
            const uint32_t kd = kdstB + (uint32_t)(((kt + 1) & 1) * SM_K) * 4;
            const uint32_t vd = vdstB + (uint32_t)(((kt + 1) & 1) * SM_V) * 4;
            const float* kp = kbp + (size_t)(kt + 1) * 64 * DIM;
            const float* vp = vbp + (size_t)(kt + 1) * 64 * DIM;
#pragma unroll
            for (int j = 0; j < 4; j++) {
                int it = t + 256 * j;
                int r = it >> 4, c4 = (it & 15) * 4;
                cp_async16(kd + (uint32_t)(r * KSTR + c4) * 4, kp + (size_t)r * DIM + c4);
                cp_async16(vd + (uint32_t)(r * VSTR + c4) * 4, vp + (size_t)r * DIM + c4);
            }
            asm volatile("cp.async.commit_group;" ::: "memory");
        }

        const float* Ks = Kd + (kt & 1) * SM_K;
        const float* Vs = Vd + (kt & 1) * SM_V;

        // S = Q K^T  (fragments via LDS.64 thanks to column-pair permutation)
        float sc[8][4];
#pragma unroll
        for (int nt = 0; nt < 8; nt++)
#pragma unroll
            for (int e = 0; e < 4; e++) sc[nt][e] = 0.0f;
#pragma unroll
        for (int d0 = 0; d0 < 64; d0 += 8) {
            float2 qa = *(const float2*)&Qs[(m0 + g) * KSTR + d0 + 2 * tg];     // a0,a2
            float2 qc = *(const float2*)&Qs[(m0 + g + 8) * KSTR + d0 + 2 * tg]; // a1,a3
            uint32_t a0 = __float_as_uint(qa.x), a2 = __float_as_uint(qa.y);
            uint32_t a1 = __float_as_uint(qc.x), a3 = __float_as_uint(qc.y);
#pragma unroll
            for (int nt = 0; nt < 8; nt++) {
                float2 kb = *(const float2*)&Ks[(nt * 8 + g) * KSTR + d0 + 2 * tg];
                mma_tf32(sc[nt], a0, a1, a2, a3,
                         __float_as_uint(kb.x), __float_as_uint(kb.y));
            }
        }

        // online softmax (base-2; scale folded into q)
        float mt0 = -1e30f, mt1 = -1e30f;
#pragma unroll
        for (int nt = 0; nt < 8; nt++) {
            mt0 = fmaxf(mt0, fmaxf(sc[nt][0], sc[nt][1]));
            mt1 = fmaxf(mt1, fmaxf(sc[nt][2], sc[nt][3]));
        }
        mt0 = fmaxf(mt0, __shfl_xor_sync(0xffffffffu, mt0, 1));
        mt0 = fmaxf(mt0, __shfl_xor_sync(0xffffffffu, mt0, 2));
        mt1 = fmaxf(mt1, __shfl_xor_sync(0xffffffffu, mt1, 1));
        mt1 = fmaxf(mt1, __shfl_xor_sync(0xffffffffu, mt1, 2));

        float mn0 = fmaxf(mrow0, mt0), mn1 = fmaxf(mrow1, mt1);
        float al0 = ex2f(mrow0 - mn0), al1 = ex2f(mrow1 - mn1);
        mrow0 = mn0; mrow1 = mn1;

        float ls0 = 0.0f, ls1 = 0.0f;
#pragma unroll
        for (int nt = 0; nt < 8; nt++) {
            sc[nt][0] = ex2f(sc[nt][0] - mn0);
            sc[nt][1] = ex2f(sc[nt][1] - mn0);
            sc[nt][2] = ex2f(sc[nt][2] - mn1);
            sc[nt][3] = ex2f(sc[nt][3] - mn1);
            ls0 += sc[nt][0] + sc[nt][1];
            ls1 += sc[nt][2] + sc[nt][3];
        }
        ls0 += __shfl_xor_sync(0xffffffffu, ls0, 1);
        ls0 += __shfl_xor_sync(0xffffffffu, ls0, 2);
        ls1 += __shfl_xor_sync(0xffffffffu, ls1, 1);
        ls1 += __shfl_xor_sync(0xffffffffu, ls1, 2);
        lrow0 = lrow0 * al0 + ls0;
        lrow1 = lrow1 * al1 + ls1;
#pragma unroll
        for (int dt = 0; dt < 8; dt++) {
            oacc[dt][0] *= al0; oacc[dt][1] *= al0;
            oacc[dt][2] *= al1; oacc[dt][3] *= al1;
        }

        // O += P V : P C-frag -> A-frag via quad shuffles (no smem round trip)
        const int src0 = 4 * g + (tg >> 1);
        const int src2 = src0 + 2;
        const bool odd = (tg & 1) != 0;
#pragma unroll
        for (int ntk = 0; ntk < 8; ntk++) {
            const int kk = ntk * 8;
            float p0 = __uint_as_float(f2tf(sc[ntk][0]));
            float p1 = __uint_as_float(f2tf(sc[ntk][1]));
            float p2 = __uint_as_float(f2tf(sc[ntk][2]));
            float p3 = __uint_as_float(f2tf(sc[ntk][3]));
            float e0 = __shfl_sync(0xffffffffu, p0, src0, 32);
            float e1 = __shfl_sync(0xffffffffu, p1, src0, 32);
            float f0 = __shfl_sync(0xffffffffu, p0, src2, 32);
            float f1 = __shfl_sync(0xffffffffu, p1, src2, 32);
            float q0 = __shfl_sync(0xffffffffu, p2, src0, 32);
            float q1 = __shfl_sync(0xffffffffu, p3, src0, 32);
            float h0 = __shfl_sync(0xffffffffu, p2, src2, 32);
            float h1 = __shfl_sync(0xffffffffu, p3, src2, 32);
            uint32_t a0 = __float_as_uint(odd ? e1 : e0);
            uint32_t a1 = __float_as_uint(odd ? q1 : q0);
            uint32_t a2 = __float_as_uint(odd ? f1 : f0);
            uint32_t a3 = __float_as_uint(odd ? h1 : h0);
#pragma unroll
            for (int dt = 0; dt < 8; dt++) {
                uint32_t b0 = __float_as_uint(Vs[(kk + tg) * VSTR + dt * 8 + g]);
                uint32_t b1 = __float_as_uint(Vs[(kk + tg + 4) * VSTR + dt * 8 + g]);
                mma_tf32(oacc[dt], a0, a1, a2, a3, b0, b1);
            }
        }
    }

    const float i0 = 1.0f / lrow0, i1 = 1.0f / lrow1;
    float* ob = gatt + ((size_t)b * LQ + qt * 128) * DIM + h * HD;
#pragma unroll
    for (int dt = 0; dt < 8; dt++) {
        const int col = dt * 8 + 2 * tg;
        float2 s0 = make_float2(oacc[dt][0] * i0, oacc[dt][1] * i0);
        float2 s1 = make_float2(oacc[dt][2] * i1, oacc[dt][3] * i1);
        *(float2*)(ob + (size_t)(m0 + g) * DIM + col)     = s0;
        *(float2*)(ob + (size_t)(m0 + g + 8) * DIM + col) = s1;
    }
}

// ---------------------------------------------------------------------------
// Launch
// ---------------------------------------------------------------------------
extern "C" void kernel_launch(void* const* d_in, const int* in_sizes, int n_in,
                              void* d_out, int out_size)
{
    const float* x   = (const float*)d_in[0];
    const float* ctx = (const float*)d_in[1];
    const float* w_q = (const float*)d_in[2];
    const float* b_q = (const float*)d_in[3];
    const float* w_k = (const float*)d_in[4];
    const float* b_k = (const float*)d_in[5];
    const float* w_v = (const float*)d_in[6];
    const float* b_v = (const float*)d_in[7];
    const float* w_o = (const float*)d_in[8];
    const float* b_o = (const float*)d_in[9];
    float* out = (float*)d_out;

    float *pq, *pk, *pv, *patt;
    cudaGetSymbolAddress((void**)&pq,   g_q);
    cudaGetSymbolAddress((void**)&pk,   g_k);
    cudaGetSymbolAddress((void**)&pv,   g_v);
    cudaGetSymbolAddress((void**)&patt, g_att);

    static int attn_smem_set = 0;
    if (!attn_smem_set) {
        cudaFuncSetAttribute(attn_mma4, cudaFuncAttributeMaxDynamicSharedMemorySize,
                             ATTN_SMEM_FLOATS * sizeof(float));
        attn_smem_set = 1;
    }

    dim3 gb(DIM / 128, MROWS / 128);   // (8, 32)
    // q: round+scale (rmode 2), permuted; k: round (1), permuted; v: round, unpermuted
    gemm_bf16_3x<<<gb, 256>>>(x,   w_q, b_q, pq, MROWS, DIM, DIM,  2, 1);
    gemm_bf16_3x<<<gb, 256>>>(ctx, w_k, b_k, pk, MROWS, DIM, DCTX, 1, 1);
    gemm_bf16_3x<<<gb, 256>>>(ctx, w_v, b_v, pv, MROWS, DIM, DCTX, 1, 0);

    dim3 ga(B_BATCH * NH, LQ / 128);   // (32, 16)
    attn_mma4<<<ga, 256, ATTN_SMEM_FLOATS * sizeof(float)>>>(pq, pk, pv, patt);

    gemm_bf16_3x<<<gb, 256>>>(patt, w_o, b_o, out, MROWS, DIM, DIM, 0, 0);
}

// round 7
// speedup vs baseline: 1.0483x; 1.0483x over previous
#include <cuda_runtime.h>
#include <cuda_bf16.h>
#include <stdint.h>
#include <math.h>

// Problem constants (CrossAttention_7756710936941)
#define B_BATCH 2
#define LQ      2048
#define LK      2048
#define DIM     1024
#define DCTX    768
#define NH      16
#define HD      64
#define MROWS   (B_BATCH * LQ)

// q pre-scale: (1/sqrt(64)) * log2(e)  (softmax done in base 2)
#define QSC 0.18033688011112042f

// Scratch (allocation-free: device globals)
__device__ float g_q[(size_t)MROWS * DIM];
__device__ float g_k[(size_t)MROWS * DIM];
__device__ float g_v[(size_t)MROWS * DIM];
// bf16 hi/lo splits of activations
__device__ __nv_bfloat16 g_xh[(size_t)MROWS * DIM],  g_xl[(size_t)MROWS * DIM];
__device__ __nv_bfloat16 g_ch[(size_t)MROWS * DCTX], g_cl[(size_t)MROWS * DCTX];
__device__ __nv_bfloat16 g_ah[(size_t)MROWS * DIM],  g_al[(size_t)MROWS * DIM];
// transposed + split weights: [N][K], K contiguous
__device__ __nv_bfloat16 g_wqh[DIM * DIM],  g_wql[DIM * DIM];
__device__ __nv_bfloat16 g_wkh[DIM * DCTX], g_wkl[DIM * DCTX];
__device__ __nv_bfloat16 g_wvh[DIM * DCTX], g_wvl[DIM * DCTX];
__device__ __nv_bfloat16 g_woh[DIM * DIM],  g_wol[DIM * DIM];

// ---------------------------------------------------------------------------
// helpers
// ---------------------------------------------------------------------------
__device__ __forceinline__ uint32_t f2tf(float x) {
    uint32_t u;
    asm("cvt.rna.tf32.f32 %0, %1;" : "=r"(u) : "f"(x));
    return u;
}
__device__ __forceinline__ float f2tf_f(float x) { return __uint_as_float(f2tf(x)); }
__device__ __forceinline__ float ex2f(float x) {
    float y;
    asm("ex2.approx.f32 %0, %1;" : "=f"(y) : "f"(x));
    return y;
}

__device__ __forceinline__ void mma_tf32(float c[4],
    uint32_t a0, uint32_t a1, uint32_t a2, uint32_t a3, uint32_t b0, uint32_t b1)
{
    asm volatile(
        "mma.sync.aligned.m16n8k8.row.col.f32.tf32.tf32.f32 "
        "{%0,%1,%2,%3},{%4,%5,%6,%7},{%8,%9},{%0,%1,%2,%3};"
        : "+f"(c[0]), "+f"(c[1]), "+f"(c[2]), "+f"(c[3])
        : "r"(a0), "r"(a1), "r"(a2), "r"(a3), "r"(b0), "r"(b1));
}

__device__ __forceinline__ void mma_bf16(float c[4],
    uint32_t a0, uint32_t a1, uint32_t a2, uint32_t a3, uint32_t b0, uint32_t b1)
{
    asm volatile(
        "mma.sync.aligned.m16n8k16.row.col.f32.bf16.bf16.f32 "
        "{%0,%1,%2,%3},{%4,%5,%6,%7},{%8,%9},{%0,%1,%2,%3};"
        : "+f"(c[0]), "+f"(c[1]), "+f"(c[2]), "+f"(c[3])
        : "r"(a0), "r"(a1), "r"(a2), "r"(a3), "r"(b0), "r"(b1));
}

__device__ __forceinline__ void cp_async16(uint32_t dst, const void* src) {
    asm volatile("cp.async.cg.shared.global [%0], [%1], 16;" :: "r"(dst), "l"(src));
}

// ---------------------------------------------------------------------------
// Elementwise bf16 hi/lo split: X f32 -> H,L bf16 (same index order)
// ---------------------------------------------------------------------------
__global__ __launch_bounds__(256) void split_hl(
    const float* __restrict__ X, __nv_bfloat16* __restrict__ H,
    __nv_bfloat16* __restrict__ L, int n4)
{
    int i = blockIdx.x * 256 + threadIdx.x;
    if (i >= n4) return;
    float4 v = *(const float4*)(X + (size_t)i * 4);
    __nv_bfloat162 h0 = __floats2bfloat162_rn(v.x, v.y);
    __nv_bfloat162 h1 = __floats2bfloat162_rn(v.z, v.w);
    __nv_bfloat162 l0 = __floats2bfloat162_rn(v.x - __bfloat162float(h0.x),
                                              v.y - __bfloat162float(h0.y));
    __nv_bfloat162 l1 = __floats2bfloat162_rn(v.z - __bfloat162float(h1.x),
                                              v.w - __bfloat162float(h1.y));
    uint2 hu, lu;
    hu.x = *(uint32_t*)&h0; hu.y = *(uint32_t*)&h1;
    lu.x = *(uint32_t*)&l0; lu.y = *(uint32_t*)&l1;
    *(uint2*)(H + (size_t)i * 4) = hu;
    *(uint2*)(L + (size_t)i * 4) = lu;
}

// ---------------------------------------------------------------------------
// Weight transpose + split: W[K,N] f32 -> Th/Tl[N,K] bf16
// ---------------------------------------------------------------------------
__global__ __launch_bounds__(256) void transpose_split(
    const float* __restrict__ W, __nv_bfloat16* __restrict__ Th,
    __nv_bfloat16* __restrict__ Tl, int K, int N)
{
    __shared__ float tile[32][33];
    const int t = threadIdx.x, tx = t & 31, g8 = t >> 5;
    const int k0 = blockIdx.x * 32, n0 = blockIdx.y * 32;
#pragma unroll
    for (int i = 0; i < 4; i++)
        tile[g8 * 4 + i][tx] = W[(size_t)(k0 + g8 * 4 + i) * N + n0 + tx];
    __syncthreads();
#pragma unroll
    for (int i = 0; i < 4; i++) {
        float v = tile[tx][g8 * 4 + i];
        __nv_bfloat16 h = __float2bfloat16_rn(v);
        size_t o = (size_t)(n0 + g8 * 4 + i) * K + k0 + tx;
        Th[o] = h;
        Tl[o] = __float2bfloat16_rn(v - __bfloat162float(h));
    }
}

// ---------------------------------------------------------------------------
// bf16 3-term GEMM on pre-split operands:
// C[M,N] = (Ah+Al)[M,K] @ (Bh+Bl)[N,K]^T + bias (drop Al*Bl), ~fp32 accuracy.
// 128x128 CTA tile, BK=32, cp.async double-buffered, 8 warps (4m x 2n).
// Smem row stride 20 words (32 k-vals = 16 words + 4 pad): frag LDS pattern
// (20g + tg) mod 32 covers all banks -> conflict-free.
// rmode: 0 = plain f32; 1 = tf32-round; 2 = tf32-round(QSC*v)
// ---------------------------------------------------------------------------
#define GKW   20
#define GROWB 80                    // bytes per smem row
#define ARRW  (128 * GKW)           // words per array (A/B, h/l)
#define STGW  (4 * ARRW)            // words per stage
#define GEMM_SMEM_BYTES (2 * STGW * 4)

__global__ __launch_bounds__(256, 2) void gemm_pre(
    const __nv_bfloat16* __restrict__ Ahg, const __nv_bfloat16* __restrict__ Alg,
    const __nv_bfloat16* __restrict__ Bhg, const __nv_bfloat16* __restrict__ Blg,
    const float* __restrict__ bias, float* __restrict__ C,
    int M, int N, int K, int rmode)
{
    extern __shared__ uint32_t gsm[];
    const uint32_t smb = (uint32_t)__cvta_generic_to_shared(gsm);

    const int t    = threadIdx.x;
    const int lane = t & 31;
    const int w    = t >> 5;
    const int g    = lane >> 2, tg = lane & 3;
    const int wm   = w >> 1,    wn = w & 1;
    const int m0   = blockIdx.y * 128, n0 = blockIdx.x * 128;

    float c[2][8][4];
#pragma unroll
    for (int i = 0; i < 2; i++)
#pragma unroll
        for (int j = 0; j < 8; j++)
#pragma unroll
            for (int e = 0; e < 4; e++) c[i][j][e] = 0.0f;

    const int lrow = t >> 1;            // 0..127
    const int lch  = (t & 1) * 16;      // element offset (16 bf16 = 32B)
    const int NC   = K / 32;

    // stage loader: 2 cp.async16 per array per thread (8 total)
    auto load_stage = [&](int cidx, int stg) {
        const uint32_t sb = smb + (uint32_t)stg * STGW * 4;
        const uint32_t rowo = (uint32_t)lrow * GROWB + (uint32_t)(t & 1) * 32;
        const size_t asrc = (size_t)(m0 + lrow) * K + cidx * 32 + lch;
        const size_t bsrc = (size_t)(n0 + lrow) * K + cidx * 32 + lch;
        cp_async16(sb + rowo,                    Ahg + asrc);
        cp_async16(sb + rowo + 16,               Ahg + asrc + 8);
        cp_async16(sb + ARRW * 4 + rowo,         Alg + asrc);
        cp_async16(sb + ARRW * 4 + rowo + 16,    Alg + asrc + 8);
        cp_async16(sb + 2 * ARRW * 4 + rowo,     Bhg + bsrc);
        cp_async16(sb + 2 * ARRW * 4 + rowo + 16, Bhg + bsrc + 8);
        cp_async16(sb + 3 * ARRW * 4 + rowo,     Blg + bsrc);
        cp_async16(sb + 3 * ARRW * 4 + rowo + 16, Blg + bsrc + 8);
        asm volatile("cp.async.commit_group;" ::: "memory");
    };

    load_stage(0, 0);

    for (int cidx = 0; cidx < NC; cidx++) {
        asm volatile("cp.async.wait_group 0;" ::: "memory");
        __syncthreads();
        if (cidx + 1 < NC) load_stage(cidx + 1, (cidx + 1) & 1);

        const uint32_t* Ah = gsm + (cidx & 1) * STGW;
        const uint32_t* Al = Ah + ARRW;
        const uint32_t* Bh = Ah + 2 * ARRW;
        const uint32_t* Bl = Ah + 3 * ARRW;

#pragma unroll
        for (int ks = 0; ks < 2; ks++) {
            const int ko = ks * 8;
            uint32_t ah[2][4], al[2][4];
#pragma unroll
            for (int mt = 0; mt < 2; mt++) {
                const int rA = wm * 32 + mt * 16;
                ah[mt][0] = Ah[(rA + g) * GKW + ko + tg];
                ah[mt][1] = Ah[(rA + g + 8) * GKW + ko + tg];
                ah[mt][2] = Ah[(rA + g) * GKW + ko + tg + 4];
                ah[mt][3] = Ah[(rA + g + 8) * GKW + ko + tg + 4];
                al[mt][0] = Al[(rA + g) * GKW + ko + tg];
                al[mt][1] = Al[(rA + g + 8) * GKW + ko + tg];
                al[mt][2] = Al[(rA + g) * GKW + ko + tg + 4];
                al[mt][3] = Al[(rA + g + 8) * GKW + ko + tg + 4];
            }
#pragma unroll
            for (int nt = 0; nt < 8; nt++) {
                const int nB = wn * 64 + nt * 8 + g;
                uint32_t bh0 = Bh[nB * GKW + ko + tg];
                uint32_t bh1 = Bh[nB * GKW + ko + tg + 4];
                uint32_t bl0 = Bl[nB * GKW + ko + tg];
                uint32_t bl1 = Bl[nB * GKW + ko + tg + 4];
#pragma unroll
                for (int mt = 0; mt < 2; mt++) {
                    mma_bf16(c[mt][nt], ah[mt][0], ah[mt][1], ah[mt][2], ah[mt][3], bh0, bh1);
                    mma_bf16(c[mt][nt], ah[mt][0], ah[mt][1], ah[mt][2], ah[mt][3], bl0, bl1);
                    mma_bf16(c[mt][nt], al[mt][0], al[mt][1], al[mt][2], al[mt][3], bh0, bh1);
                }
            }
        }
    }

    // epilogue: bias (+ optional tf32 rounding / scaling)
#pragma unroll
    for (int mt = 0; mt < 2; mt++) {
        const int r = m0 + wm * 32 + mt * 16 + g;
#pragma unroll
        for (int nt = 0; nt < 8; nt++) {
            const int col = n0 + wn * 64 + nt * 8 + 2 * tg;
            const float b0v = bias[col], b1v = bias[col + 1];
            float v0 = c[mt][nt][0] + b0v, v1 = c[mt][nt][1] + b1v;
            float v2 = c[mt][nt][2] + b0v, v3 = c[mt][nt][3] + b1v;
            if (rmode == 1) {
                v0 = f2tf_f(v0); v1 = f2tf_f(v1); v2 = f2tf_f(v2); v3 = f2tf_f(v3);
            } else if (rmode == 2) {
                v0 = f2tf_f(v0 * QSC); v1 = f2tf_f(v1 * QSC);
                v2 = f2tf_f(v2 * QSC); v3 = f2tf_f(v3 * QSC);
            }
            *(float2*)(C + (size_t)r * N + col)       = make_float2(v0, v1);
            *(float2*)(C + (size_t)(r + 8) * N + col) = make_float2(v2, v3);
        }
    }
}

// ---------------------------------------------------------------------------
// Flash cross-attention, tf32 mma.sync, cp.async double-buffered K/V.
// Inputs pre-rounded tf32 (q also pre-scaled for base-2 softmax).
// R4 access patterns (scalar frag LDS, conflict-free). Epilogue writes the
// attention output pre-split to bf16 hi/lo for the o-projection GEMM.
// ---------------------------------------------------------------------------
#define KSTR 68
#define VSTR 72
#define SM_Q  (128 * KSTR)
#define SM_K  (64 * KSTR)
#define SM_V  (64 * VSTR)
#define ATTN_SMEM_FLOATS (SM_Q + 2 * SM_K + 2 * SM_V)

__global__ __launch_bounds__(256, 2) void attn_mma5(
    const float* __restrict__ gq, const float* __restrict__ gk,
    const float* __restrict__ gv,
    __nv_bfloat16* __restrict__ oh, __nv_bfloat16* __restrict__ ol)
{
    extern __shared__ float sm[];
    float* Qs = sm;
    float* Kd = Qs + SM_Q;
    float* Vd = Kd + 2 * SM_K;
    const uint32_t smb   = (uint32_t)__cvta_generic_to_shared(sm);
    const uint32_t kdstB = smb + SM_Q * 4;
    const uint32_t vdstB = smb + (SM_Q + 2 * SM_K) * 4;

    const int t    = threadIdx.x;
    const int lane = t & 31;
    const int w    = t >> 5;
    const int g    = lane >> 2, tg = lane & 3;
    const int m0   = w * 16;
    const int bh   = blockIdx.x;
    const int b    = bh >> 4, h = bh & 15;
    const int qt   = blockIdx.y;

    const float* qb  = gq + ((size_t)b * LQ + qt * 128) * DIM + h * HD;
    const float* kbp = gk + (size_t)b * LK * DIM + h * HD;
    const float* vbp = gv + (size_t)b * LK * DIM + h * HD;

    // Q tile: verbatim copy (producer already scaled + tf32-rounded)
#pragma unroll
    for (int j = 0; j < 8; j++) {
        int it = t + 256 * j;
        int r = it >> 4, d = (it & 15) * 4;
        *(float4*)&Qs[r * KSTR + d] = *(const float4*)(qb + (size_t)r * DIM + d);
    }

    {   // prologue: async-load tile 0 into buf 0
#pragma unroll
        for (int j = 0; j < 4; j++) {
            int it = t + 256 * j;
            int r = it >> 4, c4 = (it & 15) * 4;
            cp_async16(kdstB + (uint32_t)(r * KSTR + c4) * 4, kbp + (size_t)r * DIM + c4);
            cp_async16(vdstB + (uint32_t)(r * VSTR + c4) * 4, vbp + (size_t)r * DIM + c4);
        }
        asm volatile("cp.async.commit_group;" ::: "memory");
    }

    float oacc[8][4];
#pragma unroll
    for (int dt = 0; dt < 8; dt++)
#pragma unroll
        for (int e = 0; e < 4; e++) oacc[dt][e] = 0.0f;
    float mrow0 = -1e30f, mrow1 = -1e30f, lrow0 = 0.0f, lrow1 = 0.0f;

    for (int kt = 0; kt < LK / 64; kt++) {
        asm volatile("cp.async.wait_group 0;" ::: "memory");
        __syncthreads();

        if (kt + 1 < LK / 64) {
            const uint32_t kd = kdstB + (uint32_t)(((kt + 1) & 1) * SM_K) * 4;
            const uint32_t vd = vdstB + (uint32_t)(((kt + 1) & 1) * SM_V) * 4;
            const float* kp = kbp + (size_t)(kt + 1) * 64 * DIM;
            const float* vp = vbp + (size_t)(kt + 1) * 64 * DIM;
#pragma unroll
            for (int j = 0; j < 4; j++) {
                int it = t + 256 * j;
                int r = it >> 4, c4 = (it & 15) * 4;
                cp_async16(kd + (uint32_t)(r * KSTR + c4) * 4, kp + (size_t)r * DIM + c4);
                cp_async16(vd + (uint32_t)(r * VSTR + c4) * 4, vp + (size_t)r * DIM + c4);
            }
            asm volatile("cp.async.commit_group;" ::: "memory");
        }

        const float* Ks = Kd + (kt & 1) * SM_K;
        const float* Vs = Vd + (kt & 1) * SM_V;

        // S = Q K^T  (R4 scalar frag loads, conflict-free)
        float sc[8][4];
#pragma unroll
        for (int nt = 0; nt < 8; nt++)
#pragma unroll
            for (int e = 0; e < 4; e++) sc[nt][e] = 0.0f;
#pragma unroll
        for (int d0 = 0; d0 < 64; d0 += 8) {
            uint32_t a0 = __float_as_uint(Qs[(m0 + g) * KSTR + d0 + tg]);
            uint32_t a1 = __float_as_uint(Qs[(m0 + g + 8) * KSTR + d0 + tg]);
            uint32_t a2 = __float_as_uint(Qs[(m0 + g) * KSTR + d0 + tg + 4]);
            uint32_t a3 = __float_as_uint(Qs[(m0 + g + 8) * KSTR + d0 + tg + 4]);
#pragma unroll
            for (int nt = 0; nt < 8; nt++) {
                uint32_t b0 = __float_as_uint(Ks[(nt * 8 + g) * KSTR + d0 + tg]);
                uint32_t b1 = __float_as_uint(Ks[(nt * 8 + g) * KSTR + d0 + tg + 4]);
                mma_tf32(sc[nt], a0, a1, a2, a3, b0, b1);
            }
        }

        // online softmax, base 2
        float mt0 = -1e30f, mt1 = -1e30f;
#pragma unroll
        for (int nt = 0; nt < 8; nt++) {
            mt0 = fmaxf(mt0, fmaxf(sc[nt][0], sc[nt][1]));
            mt1 = fmaxf(mt1, fmaxf(sc[nt][2], sc[nt][3]));
        }
        mt0 = fmaxf(mt0, __shfl_xor_sync(0xffffffffu, mt0, 1));
        mt0 = fmaxf(mt0, __shfl_xor_sync(0xffffffffu, mt0, 2));
        mt1 = fmaxf(mt1, __shfl_xor_sync(0xffffffffu, mt1, 1));
        mt1 = fmaxf(mt1, __shfl_xor_sync(0xffffffffu, mt1, 2));

        float mn0 = fmaxf(mrow0, mt0), mn1 = fmaxf(mrow1, mt1);
        float al0 = ex2f(mrow0 - mn0), al1 = ex2f(mrow1 - mn1);
        mrow0 = mn0; mrow1 = mn1;

        float ls0 = 0.0f, ls1 = 0.0f;
#pragma unroll
        for (int nt = 0; nt < 8; nt++) {
            sc[nt][0] = ex2f(sc[nt][0] - mn0);
            sc[nt][1] = ex2f(sc[nt][1] - mn0);
            sc[nt][2] = ex2f(sc[nt][2] - mn1);
            sc[nt][3] = ex2f(sc[nt][3] - mn1);
            ls0 += sc[nt][0] + sc[nt][1];
            ls1 += sc[nt][2] + sc[nt][3];
        }
        ls0 += __shfl_xor_sync(0xffffffffu, ls0, 1);
        ls0 += __shfl_xor_sync(0xffffffffu, ls0, 2);
        ls1 += __shfl_xor_sync(0xffffffffu, ls1, 1);
        ls1 += __shfl_xor_sync(0xffffffffu, ls1, 2);
        lrow0 = lrow0 * al0 + ls0;
        lrow1 = lrow1 * al1 + ls1;
#pragma unroll
        for (int dt = 0; dt < 8; dt++) {
            oacc[dt][0] *= al0; oacc[dt][1] *= al0;
            oacc[dt][2] *= al1; oacc[dt][3] *= al1;
        }

        // O += P V : P C-frag -> A-frag via quad shuffles
        const int src0 = 4 * g + (tg >> 1);
        const int src2 = src0 + 2;
        const bool odd = (tg & 1) != 0;
#pragma unroll
        for (int ntk = 0; ntk < 8; ntk++) {
            const int kk = ntk * 8;
            float p0 = __uint_as_float(f2tf(sc[ntk][0]));
            float p1 = __uint_as_float(f2tf(sc[ntk][1]));
            float p2 = __uint_as_float(f2tf(sc[ntk][2]));
            float p3 = __uint_as_float(f2tf(sc[ntk][3]));
            float e0 = __shfl_sync(0xffffffffu, p0, src0, 32);
            float e1 = __shfl_sync(0xffffffffu, p1, src0, 32);
            float f0 = __shfl_sync(0xffffffffu, p0, src2, 32);
            float f1 = __shfl_sync(0xffffffffu, p1, src2, 32);
            float q0 = __shfl_sync(0xffffffffu, p2, src0, 32);
            float q1 = __shfl_sync(0xffffffffu, p3, src0, 32);
            float h0 = __shfl_sync(0xffffffffu, p2, src2, 32);
            float h1 = __shfl_sync(0xffffffffu, p3, src2, 32);
            uint32_t a0 = __float_as_uint(odd ? e1 : e0);
            uint32_t a1 = __float_as_uint(odd ? q1 : q0);
            uint32_t a2 = __float_as_uint(odd ? f1 : f0);
            uint32_t a3 = __float_as_uint(odd ? h1 : h0);
#pragma unroll
            for (int dt = 0; dt < 8; dt++) {
                uint32_t b0 = __float_as_uint(Vs[(kk + tg) * VSTR + dt * 8 + g]);
                uint32_t b1 = __float_as_uint(Vs[(kk + tg + 4) * VSTR + dt * 8 + g]);
                mma_tf32(oacc[dt], a0, a1, a2, a3, b0, b1);
            }
        }
    }

    // finalize: normalize, split to bf16 hi/lo, store
    const float i0 = 1.0f / lrow0, i1 = 1.0f / lrow1;
    const size_t ob = ((size_t)b * LQ + qt * 128) * DIM + h * HD;
#pragma unroll
    for (int dt = 0; dt < 8; dt++) {
        const int col = dt * 8 + 2 * tg;
        float o00 = oacc[dt][0] * i0, o01 = oacc[dt][1] * i0;
        float o10 = oacc[dt][2] * i1, o11 = oacc[dt][3] * i1;
        __nv_bfloat162 h0 = __floats2bfloat162_rn(o00, o01);
        __nv_bfloat162 h1 = __floats2bfloat162_rn(o10, o11);
        __nv_bfloat162 l0 = __floats2bfloat162_rn(o00 - __bfloat162float(h0.x),
                                                  o01 - __bfloat162float(h0.y));
        __nv_bfloat162 l1 = __floats2bfloat162_rn(o10 - __bfloat162float(h1.x),
                                                  o11 - __bfloat162float(h1.y));
        *(__nv_bfloat162*)(oh + ob + (size_t)(m0 + g) * DIM + col)     = h0;
        *(__nv_bfloat162*)(ol + ob + (size_t)(m0 + g) * DIM + col)     = l0;
        *(__nv_bfloat162*)(oh + ob + (size_t)(m0 + g + 8) * DIM + col) = h1;
        *(__nv_bfloat162*)(ol + ob + (size_t)(m0 + g + 8) * DIM + col) = l1;
    }
}

// ---------------------------------------------------------------------------
// Launch
// ---------------------------------------------------------------------------
extern "C" void kernel_launch(void* const* d_in, const int* in_sizes, int n_in,
                              void* d_out, int out_size)
{
    const float* x   = (const float*)d_in[0];
    const float* ctx = (const float*)d_in[1];
    const float* w_q = (const float*)d_in[2];
    const float* b_q = (const float*)d_in[3];
    const float* w_k = (const float*)d_in[4];
    const float* b_k = (const float*)d_in[5];
    const float* w_v = (const float*)d_in[6];
    const float* b_v = (const float*)d_in[7];
    const float* w_o = (const float*)d_in[8];
    const float* b_o = (const float*)d_in[9];
    float* out = (float*)d_out;

    float *pq, *pk, *pv;
    cudaGetSymbolAddress((void**)&pq, g_q);
    cudaGetSymbolAddress((void**)&pk, g_k);
    cudaGetSymbolAddress((void**)&pv, g_v);
    __nv_bfloat16 *xh, *xl, *ch, *cl, *ah, *al;
    cudaGetSymbolAddress((void**)&xh, g_xh); cudaGetSymbolAddress((void**)&xl, g_xl);
    cudaGetSymbolAddress((void**)&ch, g_ch); cudaGetSymbolAddress((void**)&cl, g_cl);
    cudaGetSymbolAddress((void**)&ah, g_ah); cudaGetSymbolAddress((void**)&al, g_al);
    __nv_bfloat16 *wqh, *wql, *wkh, *wkl, *wvh, *wvl, *woh, *wol;
    cudaGetSymbolAddress((void**)&wqh, g_wqh); cudaGetSymbolAddress((void**)&wql, g_wql);
    cudaGetSymbolAddress((void**)&wkh, g_wkh); cudaGetSymbolAddress((void**)&wkl, g_wkl);
    cudaGetSymbolAddress((void**)&wvh, g_wvh); cudaGetSymbolAddress((void**)&wvl, g_wvl);
    cudaGetSymbolAddress((void**)&woh, g_woh); cudaGetSymbolAddress((void**)&wol, g_wol);

    static int attr_set = 0;
    if (!attr_set) {
        cudaFuncSetAttribute(attn_mma5, cudaFuncAttributeMaxDynamicSharedMemorySize,
                             ATTN_SMEM_FLOATS * sizeof(float));
        cudaFuncSetAttribute(gemm_pre, cudaFuncAttributeMaxDynamicSharedMemorySize,
                             GEMM_SMEM_BYTES);
        attr_set = 1;
    }

    // operand prep
    split_hl<<<(MROWS * DIM / 4 + 255) / 256, 256>>>(x,   xh, xl, MROWS * DIM / 4);
    split_hl<<<(MROWS * DCTX / 4 + 255) / 256, 256>>>(ctx, ch, cl, MROWS * DCTX / 4);
    transpose_split<<<dim3(DIM / 32,  DIM / 32), 256>>>(w_q, wqh, wql, DIM,  DIM);
    transpose_split<<<dim3(DCTX / 32, DIM / 32), 256>>>(w_k, wkh, wkl, DCTX, DIM);
    transpose_split<<<dim3(DCTX / 32, DIM / 32), 256>>>(w_v, wvh, wvl, DCTX, DIM);
    transpose_split<<<dim3(DIM / 32,  DIM / 32), 256>>>(w_o, woh, wol, DIM,  DIM);

    dim3 gb(DIM / 128, MROWS / 128);   // (8, 32)
    gemm_pre<<<gb, 256, GEMM_SMEM_BYTES>>>(xh, xl, wqh, wql, b_q, pq, MROWS, DIM, DIM,  2);
    gemm_pre<<<gb, 256, GEMM_SMEM_BYTES>>>(ch, cl, wkh, wkl, b_k, pk, MROWS, DIM, DCTX, 1);
    gemm_pre<<<gb, 256, GEMM_SMEM_BYTES>>>(ch, cl, wvh, wvl, b_v, pv, MROWS, DIM, DCTX, 1);

    dim3 ga(B_BATCH * NH, LQ / 128);   // (32, 16)
    attn_mma5<<<ga, 256, ATTN_SMEM_FLOATS * sizeof(float)>>>(pq, pk, pv, ah, al);

    gemm_pre<<<gb, 256, GEMM_SMEM_BYTES>>>(ah, al, woh, wol, b_o, out, MROWS, DIM, DIM, 0);
}

// round 8
// speedup vs baseline: 1.0515x; 1.0030x over previous
#include <cuda_runtime.h>
#include <cuda_bf16.h>
#include <stdint.h>
#include <math.h>

// Problem constants (CrossAttention_7756710936941)
#define B_BATCH 2
#define LQ      2048
#define LK      2048
#define DIM     1024
#define DCTX    768
#define NH      16
#define HD      64
#define MROWS   (B_BATCH * LQ)

// q pre-scale: (1/sqrt(64)) * log2(e)  (softmax done in base 2)
#define QSC 0.18033688011112042f

// Scratch (allocation-free: device globals)
__device__ float g_q[(size_t)MROWS * DIM];
__device__ float g_k[(size_t)MROWS * DIM];
__device__ float g_v[(size_t)MROWS * DIM];
// bf16 hi/lo splits of activations
__device__ __nv_bfloat16 g_xh[(size_t)MROWS * DIM],  g_xl[(size_t)MROWS * DIM];
__device__ __nv_bfloat16 g_ch[(size_t)MROWS * DCTX], g_cl[(size_t)MROWS * DCTX];
__device__ __nv_bfloat16 g_ah[(size_t)MROWS * DIM],  g_al[(size_t)MROWS * DIM];
// transposed + split weights: [N][K], K contiguous
__device__ __nv_bfloat16 g_wqh[DIM * DIM],  g_wql[DIM * DIM];
__device__ __nv_bfloat16 g_wkh[DIM * DCTX], g_wkl[DIM * DCTX];
__device__ __nv_bfloat16 g_wvh[DIM * DCTX], g_wvl[DIM * DCTX];
__device__ __nv_bfloat16 g_woh[DIM * DIM],  g_wol[DIM * DIM];

// ---------------------------------------------------------------------------
// helpers
// ---------------------------------------------------------------------------
__device__ __forceinline__ uint32_t f2tf(float x) {
    uint32_t u;
    asm("cvt.rna.tf32.f32 %0, %1;" : "=r"(u) : "f"(x));
    return u;
}
__device__ __forceinline__ float f2tf_f(float x) { return __uint_as_float(f2tf(x)); }
__device__ __forceinline__ float ex2f(float x) {
    float y;
    asm("ex2.approx.f32 %0, %1;" : "=f"(y) : "f"(x));
    return y;
}

__device__ __forceinline__ void mma_tf32(float c[4],
    uint32_t a0, uint32_t a1, uint32_t a2, uint32_t a3, uint32_t b0, uint32_t b1)
{
    asm volatile(
        "mma.sync.aligned.m16n8k8.row.col.f32.tf32.tf32.f32 "
        "{%0,%1,%2,%3},{%4,%5,%6,%7},{%8,%9},{%0,%1,%2,%3};"
        : "+f"(c[0]), "+f"(c[1]), "+f"(c[2]), "+f"(c[3])
        : "r"(a0), "r"(a1), "r"(a2), "r"(a3), "r"(b0), "r"(b1));
}

__device__ __forceinline__ void mma_bf16(float c[4],
    uint32_t a0, uint32_t a1, uint32_t a2, uint32_t a3, uint32_t b0, uint32_t b1)
{
    asm volatile(
        "mma.sync.aligned.m16n8k16.row.col.f32.bf16.bf16.f32 "
        "{%0,%1,%2,%3},{%4,%5,%6,%7},{%8,%9},{%0,%1,%2,%3};"
        : "+f"(c[0]), "+f"(c[1]), "+f"(c[2]), "+f"(c[3])
        : "r"(a0), "r"(a1), "r"(a2), "r"(a3), "r"(b0), "r"(b1));
}

__device__ __forceinline__ void cp_async16(uint32_t dst, const void* src) {
    asm volatile("cp.async.cg.shared.global [%0], [%1], 16;" :: "r"(dst), "l"(src));
}

// ---------------------------------------------------------------------------
// Elementwise bf16 hi/lo split: X f32 -> H,L bf16
// ---------------------------------------------------------------------------
__global__ __launch_bounds__(256) void split_hl(
    const float* __restrict__ X, __nv_bfloat16* __restrict__ H,
    __nv_bfloat16* __restrict__ L, int n4)
{
    int i = blockIdx.x * 256 + threadIdx.x;
    if (i >= n4) return;
    float4 v = *(const float4*)(X + (size_t)i * 4);
    __nv_bfloat162 h0 = __floats2bfloat162_rn(v.x, v.y);
    __nv_bfloat162 h1 = __floats2bfloat162_rn(v.z, v.w);
    __nv_bfloat162 l0 = __floats2bfloat162_rn(v.x - __bfloat162float(h0.x),
                                              v.y - __bfloat162float(h0.y));
    __nv_bfloat162 l1 = __floats2bfloat162_rn(v.z - __bfloat162float(h1.x),
                                              v.w - __bfloat162float(h1.y));
    uint2 hu, lu;
    hu.x = *(uint32_t*)&h0; hu.y = *(uint32_t*)&h1;
    lu.x = *(uint32_t*)&l0; lu.y = *(uint32_t*)&l1;
    *(uint2*)(H + (size_t)i * 4) = hu;
    *(uint2*)(L + (size_t)i * 4) = lu;
}

// ---------------------------------------------------------------------------
// Fused weight transpose + split (all 4 weights in one launch, z selects)
// W[K,N] f32 -> Th/Tl[N,K] bf16
// ---------------------------------------------------------------------------
__global__ __launch_bounds__(256) void transpose_split4(
    const float* __restrict__ w_q, const float* __restrict__ w_k,
    const float* __restrict__ w_v, const float* __restrict__ w_o,
    __nv_bfloat16* __restrict__ qh, __nv_bfloat16* __restrict__ ql,
    __nv_bfloat16* __restrict__ kh, __nv_bfloat16* __restrict__ kl,
    __nv_bfloat16* __restrict__ vh, __nv_bfloat16* __restrict__ vl,
    __nv_bfloat16* __restrict__ ohp, __nv_bfloat16* __restrict__ olp)
{
    const int z = blockIdx.z;
    const float* W;
    __nv_bfloat16 *Th, *Tl;
    int K;
    if (z == 0)      { W = w_q; Th = qh;  Tl = ql;  K = DIM;  }
    else if (z == 1) { W = w_k; Th = kh;  Tl = kl;  K = DCTX; }
    else if (z == 2) { W = w_v; Th = vh;  Tl = vl;  K = DCTX; }
    else             { W = w_o; Th = ohp; Tl = olp; K = DIM;  }
    const int k0 = blockIdx.x * 32, n0 = blockIdx.y * 32;
    if (k0 >= K) return;

    __shared__ float tile[32][33];
    const int t = threadIdx.x, tx = t & 31, g8 = t >> 5;
#pragma unroll
    for (int i = 0; i < 4; i++)
        tile[g8 * 4 + i][tx] = W[(size_t)(k0 + g8 * 4 + i) * DIM + n0 + tx];
    __syncthreads();
#pragma unroll
    for (int i = 0; i < 4; i++) {
        float v = tile[tx][g8 * 4 + i];
        __nv_bfloat16 h = __float2bfloat16_rn(v);
        size_t o = (size_t)(n0 + g8 * 4 + i) * K + k0 + tx;
        Th[o] = h;
        Tl[o] = __float2bfloat16_rn(v - __bfloat162float(h));
    }
}

// ---------------------------------------------------------------------------
// bf16 3-term GEMM body on pre-split operands (device fn).
// C[M,N] = (Ah+Al)[M,K] @ (Bh+Bl)[N,K]^T + bias (drop Al*Bl), ~fp32 accuracy.
// 128x128 CTA tile, BK=32, cp.async double-buffered, 8 warps (4m x 2n).
// Smem row stride 20 words: frag LDS (20g+tg) mod 32 conflict-free.
// rmode: 0 plain; 1 tf32-round; 2 tf32-round(QSC*v)
// ---------------------------------------------------------------------------
#define GKW   20
#define GROWB 80
#define ARRW  (128 * GKW)
#define STGW  (4 * ARRW)
#define GEMM_SMEM_BYTES (2 * STGW * 4)

__device__ __forceinline__ void gemm_body(
    uint32_t* gsm,
    const __nv_bfloat16* __restrict__ Ahg, const __nv_bfloat16* __restrict__ Alg,
    const __nv_bfloat16* __restrict__ Bhg, const __nv_bfloat16* __restrict__ Blg,
    const float* __restrict__ bias, float* __restrict__ C,
    int N, int K, int rmode, int nblk)
{
    const uint32_t smb = (uint32_t)__cvta_generic_to_shared(gsm);
    const int t    = threadIdx.x;
    const int lane = t & 31;
    const int w    = t >> 5;
    const int g    = lane >> 2, tg = lane & 3;
    const int wm   = w >> 1,    wn = w & 1;
    const int m0   = blockIdx.y * 128, n0 = nblk * 128;

    float c[2][8][4];
#pragma unroll
    for (int i = 0; i < 2; i++)
#pragma unroll
        for (int j = 0; j < 8; j++)
#pragma unroll
            for (int e = 0; e < 4; e++) c[i][j][e] = 0.0f;

    const int lrow = t >> 1;
    const int lch  = (t & 1) * 16;
    const int NC   = K / 32;

    auto load_stage = [&](int cidx, int stg) {
        const uint32_t sb = smb + (uint32_t)stg * STGW * 4;
        const uint32_t rowo = (uint32_t)lrow * GROWB + (uint32_t)(t & 1) * 32;
        const size_t asrc = (size_t)(m0 + lrow) * K + cidx * 32 + lch;
        const size_t bsrc = (size_t)(n0 + lrow) * K + cidx * 32 + lch;
        cp_async16(sb + rowo,                     Ahg + asrc);
        cp_async16(sb + rowo + 16,                Ahg + asrc + 8);
        cp_async16(sb + ARRW * 4 + rowo,          Alg + asrc);
        cp_async16(sb + ARRW * 4 + rowo + 16,     Alg + asrc + 8);
        cp_async16(sb + 2 * ARRW * 4 + rowo,      Bhg + bsrc);
        cp_async16(sb + 2 * ARRW * 4 + rowo + 16, Bhg + bsrc + 8);
        cp_async16(sb + 3 * ARRW * 4 + rowo,      Blg + bsrc);
        cp_async16(sb + 3 * ARRW * 4 + rowo + 16, Blg + bsrc + 8);
        asm volatile("cp.async.commit_group;" ::: "memory");
    };

    load_stage(0, 0);

    for (int cidx = 0; cidx < NC; cidx++) {
        asm volatile("cp.async.wait_group 0;" ::: "memory");
        __syncthreads();
        if (cidx + 1 < NC) load_stage(cidx + 1, (cidx + 1) & 1);

        const uint32_t* Ah = gsm + (cidx & 1) * STGW;
        const uint32_t* Al = Ah + ARRW;
        const uint32_t* Bh = Ah + 2 * ARRW;
        const uint32_t* Bl = Ah + 3 * ARRW;

#pragma unroll
        for (int ks = 0; ks < 2; ks++) {
            const int ko = ks * 8;
            uint32_t ah[2][4], al[2][4];
#pragma unroll
            for (int mt = 0; mt < 2; mt++) {
                const int rA = wm * 32 + mt * 16;
                ah[mt][0] = Ah[(rA + g) * GKW + ko + tg];
                ah[mt][1] = Ah[(rA + g + 8) * GKW + ko + tg];
                ah[mt][2] = Ah[(rA + g) * GKW + ko + tg + 4];
                ah[mt][3] = Ah[(rA + g + 8) * GKW + ko + tg + 4];
                al[mt][0] = Al[(rA + g) * GKW + ko + tg];
                al[mt][1] = Al[(rA + g + 8) * GKW + ko + tg];
                al[mt][2] = Al[(rA + g) * GKW + ko + tg + 4];
                al[mt][3] = Al[(rA + g + 8) * GKW + ko + tg + 4];
            }
#pragma unroll
            for (int nt = 0; nt < 8; nt++) {
                const int nB = wn * 64 + nt * 8 + g;
                uint32_t bh0 = Bh[nB * GKW + ko + tg];
                uint32_t bh1 = Bh[nB * GKW + ko + tg + 4];
                uint32_t bl0 = Bl[nB * GKW + ko + tg];
                uint32_t bl1 = Bl[nB * GKW + ko + tg + 4];
#pragma unroll
                for (int mt = 0; mt < 2; mt++) {
                    mma_bf16(c[mt][nt], ah[mt][0], ah[mt][1], ah[mt][2], ah[mt][3], bh0, bh1);
                    mma_bf16(c[mt][nt], ah[mt][0], ah[mt][1], ah[mt][2], ah[mt][3], bl0, bl1);
                    mma_bf16(c[mt][nt], al[mt][0], al[mt][1], al[mt][2], al[mt][3], bh0, bh1);
                }
            }
        }
    }

#pragma unroll
    for (int mt = 0; mt < 2; mt++) {
        const int r = m0 + wm * 32 + mt * 16 + g;
#pragma unroll
        for (int nt = 0; nt < 8; nt++) {
            const int col = n0 + wn * 64 + nt * 8 + 2 * tg;
            const float b0v = bias[col], b1v = bias[col + 1];
            float v0 = c[mt][nt][0] + b0v, v1 = c[mt][nt][1] + b1v;
            float v2 = c[mt][nt][2] + b0v, v3 = c[mt][nt][3] + b1v;
            if (rmode == 1) {
                v0 = f2tf_f(v0); v1 = f2tf_f(v1); v2 = f2tf_f(v2); v3 = f2tf_f(v3);
            } else if (rmode == 2) {
                v0 = f2tf_f(v0 * QSC); v1 = f2tf_f(v1 * QSC);
                v2 = f2tf_f(v2 * QSC); v3 = f2tf_f(v3 * QSC);
            }
            *(float2*)(C + (size_t)r * N + col)       = make_float2(v0, v1);
            *(float2*)(C + (size_t)(r + 8) * N + col) = make_float2(v2, v3);
        }
    }
}

// Fused q/k/v projection: blockIdx.x>>3 selects problem
__global__ __launch_bounds__(256, 2) void gemm_proj(
    const __nv_bfloat16* __restrict__ xh, const __nv_bfloat16* __restrict__ xl,
    const __nv_bfloat16* __restrict__ ch, const __nv_bfloat16* __restrict__ cl,
    const __nv_bfloat16* __restrict__ wqh, const __nv_bfloat16* __restrict__ wql,
    const __nv_bfloat16* __restrict__ wkh, const __nv_bfloat16* __restrict__ wkl,
    const __nv_bfloat16* __restrict__ wvh, const __nv_bfloat16* __restrict__ wvl,
    const float* __restrict__ b_q, const float* __restrict__ b_k,
    const float* __restrict__ b_v,
    float* __restrict__ pq, float* __restrict__ pk, float* __restrict__ pv)
{
    extern __shared__ uint32_t gsm[];
    const int sel = blockIdx.x >> 3, nb = blockIdx.x & 7;
    if (sel == 0)
        gemm_body(gsm, xh, xl, wqh, wql, b_q, pq, DIM, DIM,  2, nb);
    else if (sel == 1)
        gemm_body(gsm, ch, cl, wkh, wkl, b_k, pk, DIM, DCTX, 1, nb);
    else
        gemm_body(gsm, ch, cl, wvh, wvl, b_v, pv, DIM, DCTX, 1, nb);
}

// Output projection
__global__ __launch_bounds__(256, 2) void gemm_o(
    const __nv_bfloat16* __restrict__ ah, const __nv_bfloat16* __restrict__ al,
    const __nv_bfloat16* __restrict__ woh, const __nv_bfloat16* __restrict__ wol,
    const float* __restrict__ b_o, float* __restrict__ out)
{
    extern __shared__ uint32_t gsm[];
    gemm_body(gsm, ah, al, woh, wol, b_o, out, DIM, DIM, 0, blockIdx.x);
}

// ---------------------------------------------------------------------------
// Persistent flash cross-attention: grid (32, 8), each CTA does 2 q-tiles
// (qt = blockIdx.y, blockIdx.y + 8) -> 256 CTAs, one fully-resident wave.
// tf32 mma.sync, cp.async double-buffered K/V, producer-rounded inputs,
// base-2 softmax, P via quad shuffles. Output pre-split to bf16 hi/lo.
// ---------------------------------------------------------------------------
#define KSTR 68
#define VSTR 72
#define SM_Q  (128 * KSTR)
#define SM_K  (64 * KSTR)
#define SM_V  (64 * VSTR)
#define ATTN_SMEM_FLOATS (SM_Q + 2 * SM_K + 2 * SM_V)

__global__ __launch_bounds__(256, 2) void attn_mma6(
    const float* __restrict__ gq, const float* __restrict__ gk,
    const float* __restrict__ gv,
    __nv_bfloat16* __restrict__ oh, __nv_bfloat16* __restrict__ ol)
{
    extern __shared__ float sm[];
    float* Qs = sm;
    float* Kd = Qs + SM_Q;
    float* Vd = Kd + 2 * SM_K;
    const uint32_t smb   = (uint32_t)__cvta_generic_to_shared(sm);
    const uint32_t kdstB = smb + SM_Q * 4;
    const uint32_t vdstB = smb + (SM_Q + 2 * SM_K) * 4;

    const int t    = threadIdx.x;
    const int lane = t & 31;
    const int w    = t >> 5;
    const int g    = lane >> 2, tg = lane & 3;
    const int m0   = w * 16;
    const int bh   = blockIdx.x;
    const int b    = bh >> 4, h = bh & 15;

    const float* kbp = gk + (size_t)b * LK * DIM + h * HD;
    const float* vbp = gv + (size_t)b * LK * DIM + h * HD;

    for (int rep = 0; rep < 2; rep++) {
        const int qt = blockIdx.y + rep * 8;
        const float* qb = gq + ((size_t)b * LQ + qt * 128) * DIM + h * HD;

        if (rep) __syncthreads();   // prior rep fully done with Qs/Kd/Vd

        // Q tile: verbatim copy (producer already scaled + tf32-rounded)
#pragma unroll
        for (int j = 0; j < 8; j++) {
            int it = t + 256 * j;
            int r = it >> 4, d = (it & 15) * 4;
            *(float4*)&Qs[r * KSTR + d] = *(const float4*)(qb + (size_t)r * DIM + d);
        }

        {   // prologue: async-load K/V tile 0 into buf 0
#pragma unroll
            for (int j = 0; j < 4; j++) {
                int it = t + 256 * j;
                int r = it >> 4, c4 = (it & 15) * 4;
                cp_async16(kdstB + (uint32_t)(r * KSTR + c4) * 4, kbp + (size_t)r * DIM + c4);
                cp_async16(vdstB + (uint32_t)(r * VSTR + c4) * 4, vbp + (size_t)r * DIM + c4);
            }
            asm volatile("cp.async.commit_group;" ::: "memory");
        }

        float oacc[8][4];
#pragma unroll
        for (int dt = 0; dt < 8; dt++)
#pragma unroll
            for (int e = 0; e < 4; e++) oacc[dt][e] = 0.0f;
        float mrow0 = -1e30f, mrow1 = -1e30f, lrow0 = 0.0f, lrow1 = 0.0f;

        for (int kt = 0; kt < LK / 64; kt++) {
            asm volatile("cp.async.wait_group 0;" ::: "memory");
            __syncthreads();

            if (kt + 1 < LK / 64) {
                const uint32_t kd = kdstB + (uint32_t)(((kt + 1) & 1) * SM_K) * 4;
                const uint32_t vd = vdstB + (uint32_t)(((kt + 1) & 1) * SM_V) * 4;
                const float* kp = kbp + (size_t)(kt + 1) * 64 * DIM;
                const float* vp = vbp + (size_t)(kt + 1) * 64 * DIM;
#pragma unroll
                for (int j = 0; j < 4; j++) {
                    int it = t + 256 * j;
                    int r = it >> 4, c4 = (it & 15) * 4;
                    cp_async16(kd + (uint32_t)(r * KSTR + c4) * 4, kp + (size_t)r * DIM + c4);
                    cp_async16(vd + (uint32_t)(r * VSTR + c4) * 4, vp + (size_t)r * DIM + c4);
                }
                asm volatile("cp.async.commit_group;" ::: "memory");
            }

            const float* Ks = Kd + (kt & 1) * SM_K;
            const float* Vs = Vd + (kt & 1) * SM_V;

            // S = Q K^T  (scalar frag loads, conflict-free)
            float sc[8][4];
#pragma unroll
            for (int nt = 0; nt < 8; nt++)
#pragma unroll
                for (int e = 0; e < 4; e++) sc[nt][e] = 0.0f;
#pragma unroll
            for (int d0 = 0; d0 < 64; d0 += 8) {
                uint32_t a0 = __float_as_uint(Qs[(m0 + g) * KSTR + d0 + tg]);
                uint32_t a1 = __float_as_uint(Qs[(m0 + g + 8) * KSTR + d0 + tg]);
                uint32_t a2 = __float_as_uint(Qs[(m0 + g) * KSTR + d0 + tg + 4]);
                uint32_t a3 = __float_as_uint(Qs[(m0 + g + 8) * KSTR + d0 + tg + 4]);
#pragma unroll
                for (int nt = 0; nt < 8; nt++) {
                    uint32_t b0 = __float_as_uint(Ks[(nt * 8 + g) * KSTR + d0 + tg]);
                    uint32_t b1 = __float_as_uint(Ks[(nt * 8 + g) * KSTR + d0 + tg + 4]);
                    mma_tf32(sc[nt], a0, a1, a2, a3, b0, b1);
                }
            }

            // online softmax, base 2
            float mt0 = -1e30f, mt1 = -1e30f;
#pragma unroll
            for (int nt = 0; nt < 8; nt++) {
                mt0 = fmaxf(mt0, fmaxf(sc[nt][0], sc[nt][1]));
                mt1 = fmaxf(mt1, fmaxf(sc[nt][2], sc[nt][3]));
            }
            mt0 = fmaxf(mt0, __shfl_xor_sync(0xffffffffu, mt0, 1));
            mt0 = fmaxf(mt0, __shfl_xor_sync(0xffffffffu, mt0, 2));
            mt1 = fmaxf(mt1, __shfl_xor_sync(0xffffffffu, mt1, 1));
            mt1 = fmaxf(mt1, __shfl_xor_sync(0xffffffffu, mt1, 2));

            float mn0 = fmaxf(mrow0, mt0), mn1 = fmaxf(mrow1, mt1);
            float al0 = ex2f(mrow0 - mn0), al1 = ex2f(mrow1 - mn1);
            mrow0 = mn0; mrow1 = mn1;

            float ls0 = 0.0f, ls1 = 0.0f;
#pragma unroll
            for (int nt = 0; nt < 8; nt++) {
                sc[nt][0] = ex2f(sc[nt][0] - mn0);
                sc[nt][1] = ex2f(sc[nt][1] - mn0);
                sc[nt][2] = ex2f(sc[nt][2] - mn1);
                sc[nt][3] = ex2f(sc[nt][3] - mn1);
                ls0 += sc[nt][0] + sc[nt][1];
                ls1 += sc[nt][2] + sc[nt][3];
            }
            ls0 += __shfl_xor_sync(0xffffffffu, ls0, 1);
            ls0 += __shfl_xor_sync(0xffffffffu, ls0, 2);
            ls1 += __shfl_xor_sync(0xffffffffu, ls1, 1);
            ls1 += __shfl_xor_sync(0xffffffffu, ls1, 2);
            lrow0 = lrow0 * al0 + ls0;
            lrow1 = lrow1 * al1 + ls1;
#pragma unroll
            for (int dt = 0; dt < 8; dt++) {
                oacc[dt][0] *= al0; oacc[dt][1] *= al0;
                oacc[dt][2] *= al1; oacc[dt][3] *= al1;
            }

            // O += P V : P C-frag -> A-frag via quad shuffles
            const int src0 = 4 * g + (tg >> 1);
            const int src2 = src0 + 2;
            const bool odd = (tg & 1) != 0;
#pragma unroll
            for (int ntk = 0; ntk < 8; ntk++) {
                const int kk = ntk * 8;
                float p0 = __uint_as_float(f2tf(sc[ntk][0]));
                float p1 = __uint_as_float(f2tf(sc[ntk][1]));
                float p2 = __uint_as_float(f2tf(sc[ntk][2]));
                float p3 = __uint_as_float(f2tf(sc[ntk][3]));
                float e0 = __shfl_sync(0xffffffffu, p0, src0, 32);
                float e1 = __shfl_sync(0xffffffffu, p1, src0, 32);
                float f0 = __shfl_sync(0xffffffffu, p0, src2, 32);
                float f1 = __shfl_sync(0xffffffffu, p1, src2, 32);
                float q0 = __shfl_sync(0xffffffffu, p2, src0, 32);
                float q1 = __shfl_sync(0xffffffffu, p3, src0, 32);
                float h0 = __shfl_sync(0xffffffffu, p2, src2, 32);
                float h1 = __shfl_sync(0xffffffffu, p3, src2, 32);
                uint32_t a0 = __float_as_uint(odd ? e1 : e0);
                uint32_t a1 = __float_as_uint(odd ? q1 : q0);
                uint32_t a2 = __float_as_uint(odd ? f1 : f0);
                uint32_t a3 = __float_as_uint(odd ? h1 : h0);
#pragma unroll
                for (int dt = 0; dt < 8; dt++) {
                    uint32_t b0 = __float_as_uint(Vs[(kk + tg) * VSTR + dt * 8 + g]);
                    uint32_t b1 = __float_as_uint(Vs[(kk + tg + 4) * VSTR + dt * 8 + g]);
                    mma_tf32(oacc[dt], a0, a1, a2, a3, b0, b1);
                }
            }
        }

        // finalize: normalize, split to bf16 hi/lo, store
        const float i0 = 1.0f / lrow0, i1 = 1.0f / lrow1;
        const size_t ob = ((size_t)b * LQ + qt * 128) * DIM + h * HD;
#pragma unroll
        for (int dt = 0; dt < 8; dt++) {
            const int col = dt * 8 + 2 * tg;
            float o00 = oacc[dt][0] * i0, o01 = oacc[dt][1] * i0;
            float o10 = oacc[dt][2] * i1, o11 = oacc[dt][3] * i1;
            __nv_bfloat162 h0 = __floats2bfloat162_rn(o00, o01);
            __nv_bfloat162 h1 = __floats2bfloat162_rn(o10, o11);
            __nv_bfloat162 l0 = __floats2bfloat162_rn(o00 - __bfloat162float(h0.x),
                                                      o01 - __bfloat162float(h0.y));
            __nv_bfloat162 l1 = __floats2bfloat162_rn(o10 - __bfloat162float(h1.x),
                                                      o11 - __bfloat162float(h1.y));
            *(__nv_bfloat162*)(oh + ob + (size_t)(m0 + g) * DIM + col)     = h0;
            *(__nv_bfloat162*)(ol + ob + (size_t)(m0 + g) * DIM + col)     = l0;
            *(__nv_bfloat162*)(oh + ob + (size_t)(m0 + g + 8) * DIM + col) = h1;
            *(__nv_bfloat162*)(ol + ob + (size_t)(m0 + g + 8) * DIM + col) = l1;
        }
    }
}

// ---------------------------------------------------------------------------
// Launch
// ---------------------------------------------------------------------------
extern "C" void kernel_launch(void* const* d_in, const int* in_sizes, int n_in,
                              void* d_out, int out_size)
{
    const float* x   = (const float*)d_in[0];
    const float* ctx = (const float*)d_in[1];
    const float* w_q = (const float*)d_in[2];
    const float* b_q = (const float*)d_in[3];
    const float* w_k = (const float*)d_in[4];
    const float* b_k = (const float*)d_in[5];
    const float* w_v = (const float*)d_in[6];
    const float* b_v = (const float*)d_in[7];
    const float* w_o = (const float*)d_in[8];
    const float* b_o = (const float*)d_in[9];
    float* out = (float*)d_out;

    float *pq, *pk, *pv;
    cudaGetSymbolAddress((void**)&pq, g_q);
    cudaGetSymbolAddress((void**)&pk, g_k);
    cudaGetSymbolAddress((void**)&pv, g_v);
    __nv_bfloat16 *xh, *xl, *ch, *cl, *ah, *al;
    cudaGetSymbolAddress((void**)&xh, g_xh); cudaGetSymbolAddress((void**)&xl, g_xl);
    cudaGetSymbolAddress((void**)&ch, g_ch); cudaGetSymbolAddress((void**)&cl, g_cl);
    cudaGetSymbolAddress((void**)&ah, g_ah); cudaGetSymbolAddress((void**)&al, g_al);
    __nv_bfloat16 *wqh, *wql, *wkh, *wkl, *wvh, *wvl, *woh, *wol;
    cudaGetSymbolAddress((void**)&wqh, g_wqh); cudaGetSymbolAddress((void**)&wql, g_wql);
    cudaGetSymbolAddress((void**)&wkh, g_wkh); cudaGetSymbolAddress((void**)&wkl, g_wkl);
    cudaGetSymbolAddress((void**)&wvh, g_wvh); cudaGetSymbolAddress((void**)&wvl, g_wvl);
    cudaGetSymbolAddress((void**)&woh, g_woh); cudaGetSymbolAddress((void**)&wol, g_wol);

    static int attr_set = 0;
    if (!attr_set) {
        cudaFuncSetAttribute(attn_mma6, cudaFuncAttributeMaxDynamicSharedMemorySize,
                             ATTN_SMEM_FLOATS * sizeof(float));
        cudaFuncSetAttribute(gemm_proj, cudaFuncAttributeMaxDynamicSharedMemorySize,
                             GEMM_SMEM_BYTES);
        cudaFuncSetAttribute(gemm_o, cudaFuncAttributeMaxDynamicSharedMemorySize,
                             GEMM_SMEM_BYTES);
        attr_set = 1;
    }

    // operand prep
    split_hl<<<(MROWS * DIM / 4 + 255) / 256, 256>>>(x,   xh, xl, MROWS * DIM / 4);
    split_hl<<<(MROWS * DCTX / 4 + 255) / 256, 256>>>(ctx, ch, cl, MROWS * DCTX / 4);
    transpose_split4<<<dim3(DIM / 32, DIM / 32, 4), 256>>>(
        w_q, w_k, w_v, w_o, wqh, wql, wkh, wkl, wvh, wvl, woh, wol);

    // fused q/k/v projections: grid.x = 24 (8 per problem)
    gemm_proj<<<dim3(24, MROWS / 128), 256, GEMM_SMEM_BYTES>>>(
        xh, xl, ch, cl, wqh, wql, wkh, wkl, wvh, wvl, b_q, b_k, b_v, pq, pk, pv);

    // persistent attention: 256 CTAs (one resident wave), 2 q-tiles each
    attn_mma6<<<dim3(B_BATCH * NH, 8), 256, ATTN_SMEM_FLOATS * sizeof(float)>>>(
        pq, pk, pv, ah, al);

    gemm_o<<<dim3(DIM / 128, MROWS / 128), 256, GEMM_SMEM_BYTES>>>(
        ah, al, woh, wol, b_o, out);
}